// round 1
// baseline (speedup 1.0000x reference)
#include <cuda_runtime.h>
#include <math.h>

// Problem constants (from reference): N=100000, E=1600000, feat=128, hid=128, cls=64
#define MAXN 100000
#define MAXD 128

// Scratch (device globals — no allocation allowed)
__device__ float g_tmp[(size_t)MAXN * MAXD];   // GEMM output per layer
__device__ float g_h  [(size_t)MAXN * MAXD];   // aggregated hidden state
__device__ float g_dis[MAXN];                  // deg^{-1/2}
__device__ int   g_deg[MAXN];                  // degree counts (incl. self-loop)

// ---------------------------------------------------------------------------
// Degree / normalization
// ---------------------------------------------------------------------------
__global__ void k_deg_init(int n) {
    int i = blockIdx.x * blockDim.x + threadIdx.x;
    if (i < n) g_deg[i] = 1;  // self-loop
}

__global__ void k_count(const int* __restrict__ rows, int E) {
    int e = blockIdx.x * blockDim.x + threadIdx.x;
    if (e < E) atomicAdd(&g_deg[rows[e]], 1);
}

__global__ void k_dis(int n) {
    int i = blockIdx.x * blockDim.x + threadIdx.x;
    if (i < n) g_dis[i] = rsqrtf((float)g_deg[i]);
}

// ---------------------------------------------------------------------------
// GEMM: C[n, NOUT] = act(A[n,128]) @ W[128, NOUT]
// Block: 64 rows x NOUT cols, BK=32, 256 threads (16x16), 4x(NOUT/16) per thread
// ---------------------------------------------------------------------------
template <int NOUT, bool RELU>
__global__ __launch_bounds__(256) void k_gemm(
    const float* __restrict__ A, const float* __restrict__ W,
    float* __restrict__ C, int n)
{
    __shared__ float xsT[32][65];       // transposed A tile: [k][row]
    __shared__ float ws[32][NOUT];      // W tile: [k][col]

    const int tid = threadIdx.x;
    const int tx = tid & 15;            // col group
    const int ty = tid >> 4;            // row group
    const int row0 = blockIdx.x * 64;
    constexpr int CPT = NOUT / 16;      // cols per thread (8 or 4)

    float acc[4][CPT];
#pragma unroll
    for (int i = 0; i < 4; i++)
#pragma unroll
        for (int j = 0; j < CPT; j++) acc[i][j] = 0.0f;

    for (int kb = 0; kb < 128; kb += 32) {
        // Load A tile (64 x 32) -> transposed smem. 512 float4 slots, 2/thread.
#pragma unroll
        for (int s = tid; s < 512; s += 256) {
            int r  = s >> 3;      // row within tile
            int cg = s & 7;       // float4 group within 32-wide k slab
            float4 v = make_float4(0.f, 0.f, 0.f, 0.f);
            int gr = row0 + r;
            if (gr < n)
                v = *reinterpret_cast<const float4*>(A + (size_t)gr * 128 + kb + cg * 4);
            if (RELU) {
                v.x = fmaxf(v.x, 0.f); v.y = fmaxf(v.y, 0.f);
                v.z = fmaxf(v.z, 0.f); v.w = fmaxf(v.w, 0.f);
            }
            xsT[cg * 4 + 0][r] = v.x;
            xsT[cg * 4 + 1][r] = v.y;
            xsT[cg * 4 + 2][r] = v.z;
            xsT[cg * 4 + 3][r] = v.w;
        }
        // Load W tile (32 x NOUT)
#pragma unroll
        for (int s = tid; s < 32 * NOUT / 4; s += 256) {
            int r  = s / (NOUT / 4);
            int cg = s % (NOUT / 4);
            *reinterpret_cast<float4*>(&ws[r][cg * 4]) =
                *reinterpret_cast<const float4*>(W + (size_t)(kb + r) * NOUT + cg * 4);
        }
        __syncthreads();

#pragma unroll
        for (int kk = 0; kk < 32; kk++) {
            float a[4];
#pragma unroll
            for (int i = 0; i < 4; i++) a[i] = xsT[kk][ty * 4 + i];
            float b[CPT];
#pragma unroll
            for (int j = 0; j < CPT; j++) b[j] = ws[kk][tx * CPT + j];
#pragma unroll
            for (int i = 0; i < 4; i++)
#pragma unroll
                for (int j = 0; j < CPT; j++) acc[i][j] = fmaf(a[i], b[j], acc[i][j]);
        }
        __syncthreads();
    }

    // Store
#pragma unroll
    for (int i = 0; i < 4; i++) {
        int gr = row0 + ty * 4 + i;
        if (gr < n) {
#pragma unroll
            for (int j = 0; j < CPT; j += 4) {
                float4 v = make_float4(acc[i][j], acc[i][j + 1], acc[i][j + 2], acc[i][j + 3]);
                *reinterpret_cast<float4*>(C + (size_t)gr * NOUT + tx * CPT + j) = v;
            }
        }
    }
}

// ---------------------------------------------------------------------------
// Init: out[i,:] = dis[i]^2 * tmp[i,:] + bias   (self-loop term + bias)
// ---------------------------------------------------------------------------
template <int D>
__global__ void k_init(const float* __restrict__ tmp, const float* __restrict__ bias,
                       float* __restrict__ out, int n)
{
    int idx = blockIdx.x * blockDim.x + threadIdx.x;   // one float4 per thread
    int total = n * (D / 4);
    if (idx >= total) return;
    int r  = idx / (D / 4);
    int c4 = idx % (D / 4);
    float w = g_dis[r];
    w = w * w;
    float4 t = *reinterpret_cast<const float4*>(tmp + (size_t)r * D + c4 * 4);
    float4 b = *reinterpret_cast<const float4*>(bias + c4 * 4);
    float4 o;
    o.x = fmaf(w, t.x, b.x);
    o.y = fmaf(w, t.y, b.y);
    o.z = fmaf(w, t.z, b.z);
    o.w = fmaf(w, t.w, b.w);
    reinterpret_cast<float4*>(out)[idx] = o;
}

// ---------------------------------------------------------------------------
// Edge scatter: out[row,:] += dis[row]*dis[col] * tmp[col,:]
// One warp per edge; vector L2 reductions (red.global.add.v4/.v2.f32, sm_90+)
// ---------------------------------------------------------------------------
template <int D>
__global__ __launch_bounds__(256) void k_scatter(
    const int* __restrict__ rows, const int* __restrict__ cols,
    const float* __restrict__ tmp, float* __restrict__ out, int E)
{
    int warp = (blockIdx.x * blockDim.x + threadIdx.x) >> 5;
    int lane = threadIdx.x & 31;
    if (warp >= E) return;
    int r = __ldg(rows + warp);
    int c = __ldg(cols + warp);
    float w = g_dis[r] * g_dis[c];

    if (D == 128) {
        float4 v = *reinterpret_cast<const float4*>(tmp + (size_t)c * 128 + lane * 4);
        v.x *= w; v.y *= w; v.z *= w; v.w *= w;
        float* p = out + (size_t)r * 128 + lane * 4;
        asm volatile("red.global.add.v4.f32 [%0], {%1, %2, %3, %4};"
                     :: "l"(p), "f"(v.x), "f"(v.y), "f"(v.z), "f"(v.w)
                     : "memory");
    } else {
        float2 v = *reinterpret_cast<const float2*>(tmp + (size_t)c * 64 + lane * 2);
        v.x *= w; v.y *= w;
        float* p = out + (size_t)r * 64 + lane * 2;
        asm volatile("red.global.add.v2.f32 [%0], {%1, %2};"
                     :: "l"(p), "f"(v.x), "f"(v.y)
                     : "memory");
    }
}

// ---------------------------------------------------------------------------
// Launcher
// ---------------------------------------------------------------------------
extern "C" void kernel_launch(void* const* d_in, const int* in_sizes, int n_in,
                              void* d_out, int out_size)
{
    const float* x  = (const float*)d_in[0];
    const int*   ei = (const int*)  d_in[1];
    const float* W0 = (const float*)d_in[2];
    const float* b0 = (const float*)d_in[3];
    const float* W1 = (const float*)d_in[4];
    const float* b1 = (const float*)d_in[5];
    const float* W2 = (const float*)d_in[6];
    const float* b2 = (const float*)d_in[7];
    float* out = (float*)d_out;

    const int N = in_sizes[0] / 128;
    const int E = in_sizes[1] / 2;
    const int* rows = ei;        // edge_index[0]
    const int* cols = ei + E;    // edge_index[1]

    float *tmp, *h;
    cudaGetSymbolAddress((void**)&tmp, g_tmp);
    cudaGetSymbolAddress((void**)&h,   g_h);

    // Normalization coefficients
    k_deg_init<<<(N + 255) / 256, 256>>>(N);
    k_count   <<<(E + 255) / 256, 256>>>(rows, E);
    k_dis     <<<(N + 255) / 256, 256>>>(N);

    const int gemm_blocks = (N + 63) / 64;
    const int init128 = (N * 32 + 255) / 256;   // N*128/4 float4s
    const int init64  = (N * 16 + 255) / 256;
    const int scat_blocks = (E + 7) / 8;        // 8 warps/block, 1 edge/warp

    // Layer 0: h = A @ (x W0) + b0   (relu deferred to next GEMM's load)
    k_gemm<128, false><<<gemm_blocks, 256>>>(x, W0, tmp, N);
    k_init<128><<<init128, 256>>>(tmp, b0, h, N);
    k_scatter<128><<<scat_blocks, 256>>>(rows, cols, tmp, h, E);

    // Layer 1
    k_gemm<128, true><<<gemm_blocks, 256>>>(h, W1, tmp, N);
    k_init<128><<<init128, 256>>>(tmp, b1, h, N);
    k_scatter<128><<<scat_blocks, 256>>>(rows, cols, tmp, h, E);

    // Layer 2 (NCLASS=64, no relu after)
    k_gemm<64, true><<<gemm_blocks, 256>>>(h, W2, tmp, N);
    k_init<64><<<init64, 256>>>(tmp, b2, out, N);
    k_scatter<64><<<scat_blocks, 256>>>(rows, cols, tmp, out, E);
}

// round 2
// speedup vs baseline: 2.0693x; 2.0693x over previous
#include <cuda_runtime.h>
#include <math.h>

#define MAXN 100000
#define MAXE 1600000

// ---------------- scratch (device globals; no allocation allowed) ----------
__device__ float g_tmp[(size_t)MAXN * 128];     // GEMM output per layer
__device__ float g_h  [(size_t)MAXN * 128];     // aggregated hidden state
__device__ float g_dis[MAXN];                   // (deg+1)^{-1/2}
__device__ int   g_deg[MAXN];                   // real-edge counts (row)
__device__ int   g_rowptr[MAXN + 1];
__device__ int   g_cur[MAXN];
__device__ unsigned long long g_ecw[MAXE];      // packed {w_bits, col}
__device__ int   g_aux[1024];

// ---------------- packed f32x2 helpers (sm_103a FFMA2) ---------------------
__device__ __forceinline__ double pk2(float lo, float hi) {
    double d;
    asm("mov.b64 %0, {%1, %2};" : "=d"(d) : "f"(lo), "f"(hi));
    return d;
}
__device__ __forceinline__ double ffma2(double a, double b, double c) {
    double d;
    asm("fma.rn.f32x2 %0, %1, %2, %3;" : "=d"(d) : "d"(a), "d"(b), "d"(c));
    return d;
}

// ---------------- degree / normalization / CSR build -----------------------
__global__ void k_deg_zero(int n) {
    int i = blockIdx.x * blockDim.x + threadIdx.x;
    if (i < n) g_deg[i] = 0;
}
__global__ void k_count(const int* __restrict__ rows, int E) {
    int e = blockIdx.x * blockDim.x + threadIdx.x;
    if (e < E) atomicAdd(&g_deg[rows[e]], 1);
}
__global__ void k_dis(int n) {
    int i = blockIdx.x * blockDim.x + threadIdx.x;
    if (i < n) g_dis[i] = rsqrtf((float)(g_deg[i] + 1));  // +1 self-loop
}

// exclusive scan of g_deg -> g_rowptr (3-kernel, 1024-wide blocks)
__global__ void k_scan1(int n) {
    __shared__ int sh[1024];
    int tid = threadIdx.x;
    int i = blockIdx.x * 1024 + tid;
    int v = (i < n) ? g_deg[i] : 0;
    sh[tid] = v;
    __syncthreads();
#pragma unroll
    for (int off = 1; off < 1024; off <<= 1) {
        int t = (tid >= off) ? sh[tid - off] : 0;
        __syncthreads();
        sh[tid] += t;
        __syncthreads();
    }
    if (i < n) g_rowptr[i] = sh[tid] - v;  // exclusive
    if (tid == 1023) g_aux[blockIdx.x] = sh[1023];
}
__global__ void k_scan2(int nb) {
    if (threadIdx.x == 0) {
        int s = 0;
        for (int i = 0; i < nb; i++) { int t = g_aux[i]; g_aux[i] = s; s += t; }
    }
}
__global__ void k_scan3(int n, int E) {
    int i = blockIdx.x * 1024 + threadIdx.x;
    if (i < n) {
        int v = g_rowptr[i] + g_aux[blockIdx.x];
        g_rowptr[i] = v;
        g_cur[i] = v;
    }
    if (blockIdx.x == 0 && threadIdx.x == 0) g_rowptr[n] = E;
}
__global__ void k_fill(const int* __restrict__ rows, const int* __restrict__ cols, int E) {
    int e = blockIdx.x * blockDim.x + threadIdx.x;
    if (e >= E) return;
    int r = rows[e], c = cols[e];
    int pos = atomicAdd(&g_cur[r], 1);
    float w = g_dis[r] * g_dis[c];
    g_ecw[pos] = ((unsigned long long)__float_as_uint(w) << 32) | (unsigned)c;
}

// ---------------- GEMM: C = act(A[n,128]) @ W[128,BN], FFMA2 ---------------
// 128-row x BN-col block, 256 threads, 8x8 (BN=128) / 8x4 (BN=64) micro-tile.
template <int BN, bool RELU>
__global__ __launch_bounds__(256) void k_gemm(
    const float* __restrict__ A, const float* __restrict__ W,
    float* __restrict__ C, int n)
{
    extern __shared__ float sm[];
    float* Ws = sm;                    // [128][BN] whole W
    float* As = sm + 128 * BN;         // [2][32][132] transposed A tiles

    const int tid = threadIdx.x;
    const int tx = tid & 15;
    const int ty = tid >> 4;
    const int row0 = blockIdx.x * 128;
    constexpr int JP = BN / 64;        // 2 col segments for BN=128, 1 for 64

    double acc[8][JP][2];
#pragma unroll
    for (int i = 0; i < 8; i++)
#pragma unroll
        for (int s = 0; s < JP; s++) { acc[i][s][0] = 0.0; acc[i][s][1] = 0.0; }

    float4 pref[4];

    auto ldgA = [&](int kb) {
#pragma unroll
        for (int q = 0; q < 4; q++) {
            int s = tid + q * 256;
            int r = s >> 3, cg = s & 7;
            int gr = row0 + r;
            float4 v = make_float4(0.f, 0.f, 0.f, 0.f);
            if (gr < n)
                v = *reinterpret_cast<const float4*>(A + (size_t)gr * 128 + kb + cg * 4);
            if (RELU) {
                v.x = fmaxf(v.x, 0.f); v.y = fmaxf(v.y, 0.f);
                v.z = fmaxf(v.z, 0.f); v.w = fmaxf(v.w, 0.f);
            }
            pref[q] = v;
        }
    };
    auto stsA = [&](int buf) {
#pragma unroll
        for (int q = 0; q < 4; q++) {
            int s = tid + q * 256;
            int r = s >> 3, cg = s & 7;
            float* base = As + (size_t)(buf * 32) * 132;
            base[(cg * 4 + 0) * 132 + r] = pref[q].x;
            base[(cg * 4 + 1) * 132 + r] = pref[q].y;
            base[(cg * 4 + 2) * 132 + r] = pref[q].z;
            base[(cg * 4 + 3) * 132 + r] = pref[q].w;
        }
    };

    // prologue: W (whole) + first A tile
    ldgA(0);
#pragma unroll
    for (int s = tid; s < 128 * BN / 4; s += 256) {
        reinterpret_cast<float4*>(Ws)[s] = reinterpret_cast<const float4*>(W)[s];
    }
    stsA(0);
    __syncthreads();

#pragma unroll
    for (int t = 0; t < 4; t++) {
        const int buf = t & 1;
        if (t < 3) ldgA((t + 1) * 32);

        const float* Ab = As + (size_t)(buf * 32) * 132;
#pragma unroll
        for (int kk = 0; kk < 32; kk++) {
            float4 a0 = *reinterpret_cast<const float4*>(Ab + kk * 132 + ty * 4);
            float4 a1 = *reinterpret_cast<const float4*>(Ab + kk * 132 + ty * 4 + 64);
            double ad[8];
            ad[0] = pk2(a0.x, a0.x); ad[1] = pk2(a0.y, a0.y);
            ad[2] = pk2(a0.z, a0.z); ad[3] = pk2(a0.w, a0.w);
            ad[4] = pk2(a1.x, a1.x); ad[5] = pk2(a1.y, a1.y);
            ad[6] = pk2(a1.z, a1.z); ad[7] = pk2(a1.w, a1.w);
#pragma unroll
            for (int s = 0; s < JP; s++) {
                const double2 bp = *reinterpret_cast<const double2*>(
                    Ws + (size_t)(t * 32 + kk) * BN + tx * 4 + s * 64);
#pragma unroll
                for (int i = 0; i < 8; i++) {
                    acc[i][s][0] = ffma2(ad[i], bp.x, acc[i][s][0]);
                    acc[i][s][1] = ffma2(ad[i], bp.y, acc[i][s][1]);
                }
            }
        }

        if (t < 3) stsA(buf ^ 1);
        __syncthreads();
    }

    // epilogue: doubles are packed (col j, col j+1) -> direct 16B stores
#pragma unroll
    for (int i = 0; i < 8; i++) {
        int r = row0 + ty * 4 + (i & 3) + (i >> 2) * 64;
        if (r < n) {
#pragma unroll
            for (int s = 0; s < JP; s++) {
                double2 v;
                v.x = acc[i][s][0];
                v.y = acc[i][s][1];
                *reinterpret_cast<double2*>(C + (size_t)r * BN + tx * 4 + s * 64) = v;
            }
        }
    }
}

// ---------------- SPMM (CSR gather): out[r] = b + dis[r]^2*tmp[r] + sum w*tmp[c]
template <int D>
__global__ __launch_bounds__(256) void k_spmm(
    const float* __restrict__ tmp, const float* __restrict__ bias,
    float* __restrict__ out, int n)
{
    int warp = (blockIdx.x * 256 + threadIdx.x) >> 5;
    int lane = threadIdx.x & 31;
    if (warp >= n) return;
    int beg = __ldg(&g_rowptr[warp]);
    int end = __ldg(&g_rowptr[warp + 1]);
    float ds = g_dis[warp];
    float sw = ds * ds;

    if (D == 128) {
        float4 acc = *reinterpret_cast<const float4*>(bias + lane * 4);
        float4 t0 = *reinterpret_cast<const float4*>(tmp + (size_t)warp * 128 + lane * 4);
        acc.x = fmaf(sw, t0.x, acc.x); acc.y = fmaf(sw, t0.y, acc.y);
        acc.z = fmaf(sw, t0.z, acc.z); acc.w = fmaf(sw, t0.w, acc.w);
        for (int e = beg; e < end; e += 32) {
            unsigned long long cw = 0;
            if (e + lane < end) cw = __ldg(&g_ecw[e + lane]);
            int cnt = min(32, end - e);
#pragma unroll 4
            for (int j = 0; j < cnt; j++) {
                unsigned long long s = __shfl_sync(0xffffffffu, cw, j);
                int   cj = (int)(unsigned)s;
                float wj = __uint_as_float((unsigned)(s >> 32));
                float4 v = *reinterpret_cast<const float4*>(tmp + (size_t)cj * 128 + lane * 4);
                acc.x = fmaf(wj, v.x, acc.x); acc.y = fmaf(wj, v.y, acc.y);
                acc.z = fmaf(wj, v.z, acc.z); acc.w = fmaf(wj, v.w, acc.w);
            }
        }
        *reinterpret_cast<float4*>(out + (size_t)warp * 128 + lane * 4) = acc;
    } else {  // D == 64
        float2 acc = *reinterpret_cast<const float2*>(bias + lane * 2);
        float2 t0 = *reinterpret_cast<const float2*>(tmp + (size_t)warp * 64 + lane * 2);
        acc.x = fmaf(sw, t0.x, acc.x); acc.y = fmaf(sw, t0.y, acc.y);
        for (int e = beg; e < end; e += 32) {
            unsigned long long cw = 0;
            if (e + lane < end) cw = __ldg(&g_ecw[e + lane]);
            int cnt = min(32, end - e);
#pragma unroll 4
            for (int j = 0; j < cnt; j++) {
                unsigned long long s = __shfl_sync(0xffffffffu, cw, j);
                int   cj = (int)(unsigned)s;
                float wj = __uint_as_float((unsigned)(s >> 32));
                float2 v = *reinterpret_cast<const float2*>(tmp + (size_t)cj * 64 + lane * 2);
                acc.x = fmaf(wj, v.x, acc.x); acc.y = fmaf(wj, v.y, acc.y);
            }
        }
        *reinterpret_cast<float2*>(out + (size_t)warp * 64 + lane * 2) = acc;
    }
}

// ---------------- launcher --------------------------------------------------
extern "C" void kernel_launch(void* const* d_in, const int* in_sizes, int n_in,
                              void* d_out, int out_size)
{
    const float* x  = (const float*)d_in[0];
    const int*   ei = (const int*)  d_in[1];
    const float* W0 = (const float*)d_in[2];
    const float* b0 = (const float*)d_in[3];
    const float* W1 = (const float*)d_in[4];
    const float* b1 = (const float*)d_in[5];
    const float* W2 = (const float*)d_in[6];
    const float* b2 = (const float*)d_in[7];
    float* out = (float*)d_out;

    const int N = in_sizes[0] / 128;
    const int E = in_sizes[1] / 2;
    const int* rows = ei;
    const int* cols = ei + E;

    float *tmp, *h;
    cudaGetSymbolAddress((void**)&tmp, g_tmp);
    cudaGetSymbolAddress((void**)&h,   g_h);

    // opt-in dynamic smem for the GEMMs (idempotent; legal during capture)
    static bool attr_done = false;
    const int smem128 = 128 * 128 * 4 + 2 * 32 * 132 * 4;  // 99328
    const int smem64  = 128 *  64 * 4 + 2 * 32 * 132 * 4;  // 66560
    if (!attr_done) {
        cudaFuncSetAttribute(k_gemm<128, false>, cudaFuncAttributeMaxDynamicSharedMemorySize, smem128);
        cudaFuncSetAttribute(k_gemm<128, true>,  cudaFuncAttributeMaxDynamicSharedMemorySize, smem128);
        cudaFuncSetAttribute(k_gemm<64,  true>,  cudaFuncAttributeMaxDynamicSharedMemorySize, smem64);
        attr_done = true;
    }

    const int nb1024 = (N + 1023) / 1024;

    // CSR build (reused by all 3 layers)
    k_deg_zero<<<(N + 255) / 256, 256>>>(N);
    k_count   <<<(E + 255) / 256, 256>>>(rows, E);
    k_dis     <<<(N + 255) / 256, 256>>>(N);
    k_scan1   <<<nb1024, 1024>>>(N);
    k_scan2   <<<1, 32>>>(nb1024);
    k_scan3   <<<nb1024, 1024>>>(N, E);
    k_fill    <<<(E + 255) / 256, 256>>>(rows, cols, E);

    const int gemm_blocks = (N + 127) / 128;
    const int spmm_blocks = (N + 7) / 8;   // 8 warps/block, 1 row/warp

    // Layer 0
    k_gemm<128, false><<<gemm_blocks, 256, smem128>>>(x, W0, tmp, N);
    k_spmm<128><<<spmm_blocks, 256>>>(tmp, b0, h, N);
    // Layer 1 (relu fused into GEMM A-load)
    k_gemm<128, true><<<gemm_blocks, 256, smem128>>>(h, W1, tmp, N);
    k_spmm<128><<<spmm_blocks, 256>>>(tmp, b1, h, N);
    // Layer 2 (NCLASS = 64)
    k_gemm<64, true><<<gemm_blocks, 256, smem64>>>(h, W2, tmp, N);
    k_spmm<64><<<spmm_blocks, 256>>>(tmp, b2, out, N);
}

// round 4
// speedup vs baseline: 2.5957x; 1.2544x over previous
#include <cuda_runtime.h>
#include <cuda_bf16.h>
#include <cstdint>
#include <math.h>

#define MAXN 100000
#define MAXE 1600000
#define PITCH 136   // bf16 elements per smem/W-image row (128 + 8 pad)

// ---------------- scratch (device globals; no allocation allowed) ----------
__device__ __nv_bfloat16 g_tmpb[(size_t)MAXN * 128];  // GEMM output (bf16)
__device__ float g_h  [(size_t)MAXN * 128];           // aggregated hidden (fp32)
__device__ float g_dis[MAXN];
__device__ int   g_deg[MAXN];
__device__ int   g_rowptr[MAXN + 1];
__device__ int   g_cur[MAXN];
__device__ unsigned long long g_ecw[MAXE];            // packed {w_bits, col}
__device__ int   g_aux[1024];
// W^T images, [BN rows][PITCH cols] bf16, hi/mid split
__device__ __nv_bfloat16 g_w0img[2][128 * PITCH];
__device__ __nv_bfloat16 g_w1img[2][128 * PITCH];
__device__ __nv_bfloat16 g_w2img[2][64 * PITCH];

// ---------------- helpers ---------------------------------------------------
__device__ __forceinline__ uint32_t smem_u32(const void* p) {
    uint32_t a;
    asm("{ .reg .u64 t; cvta.to.shared.u64 t, %1; cvt.u32.u64 %0, t; }" : "=r"(a) : "l"(p));
    return a;
}
__device__ __forceinline__ void ldmx4(uint32_t& a0, uint32_t& a1, uint32_t& a2, uint32_t& a3,
                                      uint32_t addr) {
    asm volatile("ldmatrix.sync.aligned.m8n8.x4.shared.b16 {%0,%1,%2,%3}, [%4];"
                 : "=r"(a0), "=r"(a1), "=r"(a2), "=r"(a3) : "r"(addr));
}
__device__ __forceinline__ void ldmx2(uint32_t& b0, uint32_t& b1, uint32_t addr) {
    asm volatile("ldmatrix.sync.aligned.m8n8.x2.shared.b16 {%0,%1}, [%2];"
                 : "=r"(b0), "=r"(b1) : "r"(addr));
}
__device__ __forceinline__ void mma16816(float* c, uint32_t a0, uint32_t a1, uint32_t a2,
                                         uint32_t a3, uint32_t b0, uint32_t b1) {
    asm volatile("mma.sync.aligned.m16n8k16.row.col.f32.bf16.bf16.f32 "
                 "{%0,%1,%2,%3}, {%4,%5,%6,%7}, {%8,%9}, {%0,%1,%2,%3};"
                 : "+f"(c[0]), "+f"(c[1]), "+f"(c[2]), "+f"(c[3])
                 : "r"(a0), "r"(a1), "r"(a2), "r"(a3), "r"(b0), "r"(b1));
}

// ---------------- degree / normalization / CSR build -----------------------
__global__ void k_deg_zero(int n) {
    int i = blockIdx.x * blockDim.x + threadIdx.x;
    if (i < n) g_deg[i] = 0;
}
__global__ void k_count(const int* __restrict__ rows, int E) {
    int e = blockIdx.x * blockDim.x + threadIdx.x;
    if (e < E) atomicAdd(&g_deg[rows[e]], 1);
}
__global__ void k_dis(int n) {
    int i = blockIdx.x * blockDim.x + threadIdx.x;
    if (i < n) g_dis[i] = rsqrtf((float)(g_deg[i] + 1));
}
__global__ void k_scan1(int n) {
    __shared__ int sh[1024];
    int tid = threadIdx.x;
    int i = blockIdx.x * 1024 + tid;
    int v = (i < n) ? g_deg[i] : 0;
    sh[tid] = v;
    __syncthreads();
#pragma unroll
    for (int off = 1; off < 1024; off <<= 1) {
        int t = (tid >= off) ? sh[tid - off] : 0;
        __syncthreads();
        sh[tid] += t;
        __syncthreads();
    }
    if (i < n) g_rowptr[i] = sh[tid] - v;
    if (tid == 1023) g_aux[blockIdx.x] = sh[1023];
}
__global__ void k_scan2(int nb) {
    if (threadIdx.x == 0) {
        int s = 0;
        for (int i = 0; i < nb; i++) { int t = g_aux[i]; g_aux[i] = s; s += t; }
    }
}
__global__ void k_scan3(int n, int E) {
    int i = blockIdx.x * 1024 + threadIdx.x;
    if (i < n) {
        int v = g_rowptr[i] + g_aux[blockIdx.x];
        g_rowptr[i] = v;
        g_cur[i] = v;
    }
    if (blockIdx.x == 0 && threadIdx.x == 0) g_rowptr[n] = E;
}
__global__ void k_fill(const int* __restrict__ rows, const int* __restrict__ cols, int E) {
    int e = blockIdx.x * blockDim.x + threadIdx.x;
    if (e >= E) return;
    int r = rows[e], c = cols[e];
    int pos = atomicAdd(&g_cur[r], 1);
    float w = g_dis[r] * g_dis[c];
    g_ecw[pos] = ((unsigned long long)__float_as_uint(w) << 32) | (unsigned)c;
}

// ---------------- weight split: W[128][BN] fp32 -> W^T hi/mid images -------
template <int BN>
__global__ void k_splitW(const float* __restrict__ W,
                         __nv_bfloat16* __restrict__ hi, __nv_bfloat16* __restrict__ mid)
{
    int idx = blockIdx.x * blockDim.x + threadIdx.x;
    if (idx >= 128 * BN) return;
    int k = idx / BN, j = idx % BN;
    float v = W[idx];
    __nv_bfloat16 h = __float2bfloat16_rn(v);
    float r = v - __bfloat162float(h);
    hi [j * PITCH + k] = h;
    mid[j * PITCH + k] = __float2bfloat16_rn(r);
}

// ---------------- GEMM via mma.sync bf16 split ------------------------------
// C[n,BN](bf16) = act(A[n,128]) @ W[128,BN];  64-row CTA tile, 8 warps.
// Products: Ahi*Whi + Ahi*Wmid + Ami*Whi (fp32 accum).
template <int BN, bool RELU>
__global__ __launch_bounds__(256) void k_gemm_mma(
    const float* __restrict__ A,
    const __nv_bfloat16* __restrict__ WThi, const __nv_bfloat16* __restrict__ WTmid,
    __nv_bfloat16* __restrict__ C, int n)
{
    extern __shared__ __nv_bfloat16 sm[];
    __nv_bfloat16* Ahi = sm;                       // [64][PITCH]
    __nv_bfloat16* Ami = sm + 64 * PITCH;
    __nv_bfloat16* Whi = sm + 2 * 64 * PITCH;      // [BN][PITCH]

    const int tid = threadIdx.x;
    const int wid = tid >> 5;
    const int lane = tid & 31;
    const int row0 = blockIdx.x * 64;
    constexpr int NT = BN / 32;                    // n8-tiles per warp (4 or 2)
    constexpr uint32_t AOFF = 64 * PITCH * 2;      // bytes Ahi -> Ami
    constexpr uint32_t WOFF = BN * PITCH * 2;      // bytes Whi -> Wmid

    // copy W images (flat; pad preserved — images are pitch-exact)
    {
        const float4* s0 = (const float4*)WThi;
        const float4* s1 = (const float4*)WTmid;
        float4* d0 = (float4*)Whi;
        float4* d1 = (float4*)(Whi + BN * PITCH);
        constexpr int NV = BN * PITCH / 8;         // float4 count per image
#pragma unroll
        for (int i = tid; i < NV; i += 256) { d0[i] = s0[i]; d1[i] = s1[i]; }
    }

    // convert A tile: 64 rows x 128 cols fp32 -> hi/mid bf16
    {
        const int r = tid >> 2;
        const int q = tid & 3;
        const int gr = row0 + r;
        const bool valid = gr < n;
        const float4* arow = (const float4*)(A + (size_t)(valid ? gr : 0) * 128);
#pragma unroll
        for (int i = 0; i < 8; i++) {
            int c = q * 32 + i * 4;
            float4 v = valid ? arow[c >> 2] : make_float4(0.f, 0.f, 0.f, 0.f);
            if (RELU) {
                v.x = fmaxf(v.x, 0.f); v.y = fmaxf(v.y, 0.f);
                v.z = fmaxf(v.z, 0.f); v.w = fmaxf(v.w, 0.f);
            }
            __nv_bfloat162 h01 = __float22bfloat162_rn(make_float2(v.x, v.y));
            __nv_bfloat162 h23 = __float22bfloat162_rn(make_float2(v.z, v.w));
            float2 f01 = __bfloat1622float2(h01);
            float2 f23 = __bfloat1622float2(h23);
            __nv_bfloat162 m01 = __float22bfloat162_rn(make_float2(v.x - f01.x, v.y - f01.y));
            __nv_bfloat162 m23 = __float22bfloat162_rn(make_float2(v.z - f23.x, v.w - f23.y));
            *reinterpret_cast<uint2*>(Ahi + r * PITCH + c) =
                make_uint2(reinterpret_cast<uint32_t&>(h01), reinterpret_cast<uint32_t&>(h23));
            *reinterpret_cast<uint2*>(Ami + r * PITCH + c) =
                make_uint2(reinterpret_cast<uint32_t&>(m01), reinterpret_cast<uint32_t&>(m23));
        }
    }
    __syncthreads();

    const int warpM = wid & 1;     // 2 x 32 rows
    const int warpN = wid >> 1;    // 4 x (BN/4) cols

    float acc[2][NT][4];
#pragma unroll
    for (int mi = 0; mi < 2; mi++)
#pragma unroll
        for (int ni = 0; ni < NT; ni++)
#pragma unroll
            for (int j = 0; j < 4; j++) acc[mi][ni][j] = 0.f;

    // ldmatrix base addresses (col offset advances by 32B per k16 step)
    uint32_t a_addr[2], b_addr[NT];
#pragma unroll
    for (int mi = 0; mi < 2; mi++) {
        int r = warpM * 32 + mi * 16 + (lane & 15);
        int c = ((lane >> 4) << 3);
        a_addr[mi] = smem_u32(Ahi + r * PITCH + c);
    }
#pragma unroll
    for (int ni = 0; ni < NT; ni++) {
        int r = warpN * (BN / 4) + ni * 8 + (lane & 7);
        int c = ((lane >> 3) & 1) * 8;
        b_addr[ni] = smem_u32(Whi + r * PITCH + c);
    }

#pragma unroll
    for (int p = 0; p < 3; p++) {
        const uint32_t ao = (p == 2) ? AOFF : 0u;
        const uint32_t bo = (p == 1) ? WOFF : 0u;
#pragma unroll
        for (int kk = 0; kk < 8; kk++) {
            const uint32_t ko = kk * 32;           // 16 bf16 = 32 bytes
            uint32_t a[2][4];
#pragma unroll
            for (int mi = 0; mi < 2; mi++)
                ldmx4(a[mi][0], a[mi][1], a[mi][2], a[mi][3], a_addr[mi] + ao + ko);
            uint32_t b[NT][2];
#pragma unroll
            for (int ni = 0; ni < NT; ni++)
                ldmx2(b[ni][0], b[ni][1], b_addr[ni] + bo + ko);
#pragma unroll
            for (int mi = 0; mi < 2; mi++)
#pragma unroll
                for (int ni = 0; ni < NT; ni++)
                    mma16816(acc[mi][ni], a[mi][0], a[mi][1], a[mi][2], a[mi][3],
                             b[ni][0], b[ni][1]);
        }
    }

    // epilogue: bf16 stores
#pragma unroll
    for (int mi = 0; mi < 2; mi++) {
        int r = row0 + warpM * 32 + mi * 16 + (lane >> 2);
#pragma unroll
        for (int ni = 0; ni < NT; ni++) {
            int c = warpN * (BN / 4) + ni * 8 + (lane & 3) * 2;
            if (r < n) {
                __nv_bfloat162 v = __float22bfloat162_rn(make_float2(acc[mi][ni][0], acc[mi][ni][1]));
                *reinterpret_cast<__nv_bfloat162*>(C + (size_t)r * BN + c) = v;
            }
            if (r + 8 < n) {
                __nv_bfloat162 v = __float22bfloat162_rn(make_float2(acc[mi][ni][2], acc[mi][ni][3]));
                *reinterpret_cast<__nv_bfloat162*>(C + (size_t)(r + 8) * BN + c) = v;
            }
        }
    }
}

// ---------------- SPMM (CSR gather, bf16 payload, fp32 accum) --------------
// out[r] = bias + dis[r]^2 * tmp[r] + sum_j w_j * tmp[col_j]
template <int D>
__global__ __launch_bounds__(256) void k_spmm(
    const __nv_bfloat16* __restrict__ tmp, const float* __restrict__ bias,
    float* __restrict__ out, int n)
{
    int warp = (blockIdx.x * 256 + threadIdx.x) >> 5;
    int lane = threadIdx.x & 31;
    if (warp >= n) return;
    int beg = __ldg(&g_rowptr[warp]);
    int end = __ldg(&g_rowptr[warp + 1]);
    float ds = g_dis[warp];
    float sw = ds * ds;

    if (D == 128) {
        float4 acc = *reinterpret_cast<const float4*>(bias + lane * 4);
        {
            uint2 u = *reinterpret_cast<const uint2*>(tmp + (size_t)warp * 128 + lane * 4);
            float2 p0 = __bfloat1622float2(reinterpret_cast<__nv_bfloat162&>(u.x));
            float2 p1 = __bfloat1622float2(reinterpret_cast<__nv_bfloat162&>(u.y));
            acc.x = fmaf(sw, p0.x, acc.x); acc.y = fmaf(sw, p0.y, acc.y);
            acc.z = fmaf(sw, p1.x, acc.z); acc.w = fmaf(sw, p1.y, acc.w);
        }
        for (int e = beg; e < end; e += 32) {
            unsigned long long cw = 0;
            if (e + lane < end) cw = __ldg(&g_ecw[e + lane]);
            int cnt = min(32, end - e);
#pragma unroll 4
            for (int j = 0; j < cnt; j++) {
                unsigned long long s = __shfl_sync(0xffffffffu, cw, j);
                int   cj = (int)(unsigned)s;
                float wj = __uint_as_float((unsigned)(s >> 32));
                uint2 u = *reinterpret_cast<const uint2*>(tmp + (size_t)cj * 128 + lane * 4);
                float2 p0 = __bfloat1622float2(reinterpret_cast<__nv_bfloat162&>(u.x));
                float2 p1 = __bfloat1622float2(reinterpret_cast<__nv_bfloat162&>(u.y));
                acc.x = fmaf(wj, p0.x, acc.x); acc.y = fmaf(wj, p0.y, acc.y);
                acc.z = fmaf(wj, p1.x, acc.z); acc.w = fmaf(wj, p1.y, acc.w);
            }
        }
        *reinterpret_cast<float4*>(out + (size_t)warp * 128 + lane * 4) = acc;
    } else {  // D == 64
        float2 acc = *reinterpret_cast<const float2*>(bias + lane * 2);
        {
            uint32_t u = *reinterpret_cast<const uint32_t*>(tmp + (size_t)warp * 64 + lane * 2);
            float2 p = __bfloat1622float2(reinterpret_cast<__nv_bfloat162&>(u));
            acc.x = fmaf(sw, p.x, acc.x); acc.y = fmaf(sw, p.y, acc.y);
        }
        for (int e = beg; e < end; e += 32) {
            unsigned long long cw = 0;
            if (e + lane < end) cw = __ldg(&g_ecw[e + lane]);
            int cnt = min(32, end - e);
#pragma unroll 4
            for (int j = 0; j < cnt; j++) {
                unsigned long long s = __shfl_sync(0xffffffffu, cw, j);
                int   cj = (int)(unsigned)s;
                float wj = __uint_as_float((unsigned)(s >> 32));
                uint32_t u = *reinterpret_cast<const uint32_t*>(tmp + (size_t)cj * 64 + lane * 2);
                float2 p = __bfloat1622float2(reinterpret_cast<__nv_bfloat162&>(u));
                acc.x = fmaf(wj, p.x, acc.x); acc.y = fmaf(wj, p.y, acc.y);
            }
        }
        *reinterpret_cast<float2*>(out + (size_t)warp * 64 + lane * 2) = acc;
    }
}

// ---------------- launcher --------------------------------------------------
extern "C" void kernel_launch(void* const* d_in, const int* in_sizes, int n_in,
                              void* d_out, int out_size)
{
    const float* x  = (const float*)d_in[0];
    const int*   ei = (const int*)  d_in[1];
    const float* W0 = (const float*)d_in[2];
    const float* b0 = (const float*)d_in[3];
    const float* W1 = (const float*)d_in[4];
    const float* b1 = (const float*)d_in[5];
    const float* W2 = (const float*)d_in[6];
    const float* b2 = (const float*)d_in[7];
    float* out = (float*)d_out;

    const int N = in_sizes[0] / 128;
    const int E = in_sizes[1] / 2;
    const int* rows = ei;
    const int* cols = ei + E;

    __nv_bfloat16 *tmpb, *w0img, *w1img, *w2img;
    float* h;
    cudaGetSymbolAddress((void**)&tmpb,  g_tmpb);
    cudaGetSymbolAddress((void**)&h,     g_h);
    cudaGetSymbolAddress((void**)&w0img, g_w0img);
    cudaGetSymbolAddress((void**)&w1img, g_w1img);
    cudaGetSymbolAddress((void**)&w2img, g_w2img);
    __nv_bfloat16* w0_hi = w0img; __nv_bfloat16* w0_mi = w0img + 128 * PITCH;
    __nv_bfloat16* w1_hi = w1img; __nv_bfloat16* w1_mi = w1img + 128 * PITCH;
    __nv_bfloat16* w2_hi = w2img; __nv_bfloat16* w2_mi = w2img + 64 * PITCH;

    const int smem128 = (2 * 64 + 2 * 128) * PITCH * 2;   // 104448
    const int smem64  = (2 * 64 + 2 * 64)  * PITCH * 2;   // 69632
    static bool attr_done = false;
    if (!attr_done) {
        cudaFuncSetAttribute(k_gemm_mma<128, false>, cudaFuncAttributeMaxDynamicSharedMemorySize, smem128);
        cudaFuncSetAttribute(k_gemm_mma<128, true>,  cudaFuncAttributeMaxDynamicSharedMemorySize, smem128);
        cudaFuncSetAttribute(k_gemm_mma<64,  true>,  cudaFuncAttributeMaxDynamicSharedMemorySize, smem64);
        attr_done = true;
    }

    const int nb1024 = (N + 1023) / 1024;

    // CSR build (reused by all 3 layers)
    k_deg_zero<<<(N + 255) / 256, 256>>>(N);
    k_count   <<<(E + 255) / 256, 256>>>(rows, E);
    k_dis     <<<(N + 255) / 256, 256>>>(N);
    k_scan1   <<<nb1024, 1024>>>(N);
    k_scan2   <<<1, 32>>>(nb1024);
    k_scan3   <<<nb1024, 1024>>>(N, E);
    k_fill    <<<(E + 255) / 256, 256>>>(rows, cols, E);

    // weight splits (transposed + padded bf16 images)
    k_splitW<128><<<(128 * 128 + 255) / 256, 256>>>(W0, w0_hi, w0_mi);
    k_splitW<128><<<(128 * 128 + 255) / 256, 256>>>(W1, w1_hi, w1_mi);
    k_splitW<64> <<<(128 * 64  + 255) / 256, 256>>>(W2, w2_hi, w2_mi);

    const int gemm_blocks = (N + 63) / 64;
    const int spmm_blocks = (N + 7) / 8;

    // Layer 0
    k_gemm_mma<128, false><<<gemm_blocks, 256, smem128>>>(x, w0_hi, w0_mi, tmpb, N);
    k_spmm<128><<<spmm_blocks, 256>>>(tmpb, b0, h, N);
    // Layer 1 (relu fused into GEMM A conversion)
    k_gemm_mma<128, true><<<gemm_blocks, 256, smem128>>>(h, w1_hi, w1_mi, tmpb, N);
    k_spmm<128><<<spmm_blocks, 256>>>(tmpb, b1, h, N);
    // Layer 2 (NCLASS = 64)
    k_gemm_mma<64, true><<<gemm_blocks, 256, smem64>>>(h, w2_hi, w2_mi, tmpb, N);
    k_spmm<64><<<spmm_blocks, 256>>>(tmpb, b2, out, N);
}